// round 16
// baseline (speedup 1.0000x reference)
#include <cuda_runtime.h>
#include <math.h>

// ---------------------------------------------------------------------------
// PhotonicDelayReservoirAdaptive — sparse delay-tap reservoir scan, sm_103a.
//
//   fb[b,s]  = sum_k softmax(tapw)[k] * sum_r h[b, t-d_k, r] * W_fb[k,r,s]
//   h_new    = 0.9*h + 0.1*tanh(x[b,t]*W_in[s] + fb[b,s] + bias[s])
//
// R15 = R14 engine + BATCH-PAIR amortization:
//  R12/R14 showed a ~5.4K cyc/step floor at 512 thr that is NOT issue-bound
//  (cutting 25% of instructions changed nothing) -> LSU-op/latency floor.
//  Serve 2 batches per LDS: 32 CTAs, each owns batches {2b, 2b+1}; hist is
//  float2 (batch-packed) so the gather does LDS.64 + 2 FFMA per entry at
//  unchanged LDG/LOP3/addressing cost.
//  * 512 threads; warp wg owns 16 columns; column c split across 2 sub-lanes
//    by entry parity (sub = e&1), counting-sorted by rotated key to stagger
//    banks; sub-lane also owns one batch of the pair in the epilogue.
//  * Schedule in GMEM via __ldg (L1-resident), quad-interleaved
//    [wg][quad][lane][4] -> one coalesced 512B LDG.128 per warp per quad.
//    COMPENSATED packing (validated: rel_err 8.0e-6): raw word = f32 weight
//    (within half bit-11 ulp), low 11 bits = hist index.
//  * History prefetch via __ldcg (L2-direct, zero L1 pollution).
//  * hist[2][5*256] float2 double buffer (20KB static); slot0 = row t-1
//    (both batches, written by the two sub-lanes), slots 1-4 = rows
//    t-{4,24,96,168} x 2 batches prefetched one step early.
//    ONE __syncthreads per step; NO cross-CTA sync.
// ---------------------------------------------------------------------------

#define T_LEN     2048
#define R_DIM     256
#define N_TAPS    5
#define NTH       512
#define NWARP     16
#define NCTA      32       // one CTA per batch PAIR
#define CAP_SUB   96       // entries per sub-list (mean 64, sigma 7.6 -> +4.2s)
#define CAP_QUAD  24       // quad-blocks per warp cap

#define SCHED_WORDS (NWARP * CAP_QUAD * 128)   // 49152 words = 196608 B

__device__ __align__(16) unsigned g_sched[SCHED_WORDS];
__device__ int g_warpBase[NWARP];    // quad-block base per warp
__device__ int g_warpQuads[NWARP];   // quad count per warp (uniform trips)

// ---------------------------------------------------------------------------
// Builder: 1 CTA, 256 threads, thread = output column c (wg=c/16, cl=c%16).
// Identical to R14 (schedule is batch-independent).
// ---------------------------------------------------------------------------
__global__ void build_kernel(const float* __restrict__ W_fb,
                             const float* __restrict__ tapw) {
    __shared__ int scnt[R_DIM][32];   // [col][sub*16 + key]
    __shared__ int swMaxE[NWARP];
    __shared__ int sBase[NWARP];

    const int c  = threadIdx.x;
    const int wg = c >> 4;
    const int cl = c & 15;

    // softmax of tap weights (exact, redundant per thread)
    float tw[N_TAPS];
    {
        float m = tapw[0];
        #pragma unroll
        for (int k = 1; k < N_TAPS; k++) m = fmaxf(m, tapw[k]);
        float sum = 0.f;
        #pragma unroll
        for (int k = 0; k < N_TAPS; k++) { tw[k] = expf(tapw[k] - m); sum += tw[k]; }
        #pragma unroll
        for (int k = 0; k < N_TAPS; k++) tw[k] /= sum;
    }

    if (c < NWARP) swMaxE[c] = 0;
    // pad-fill: word -> its own lane slot: value is a denormal (~0 with FTZ)
    // and the hist index (= lane) is distinct per lane -> conflict-free.
    for (int i = c; i < SCHED_WORDS; i += R_DIM)
        g_sched[i] = (unsigned)((i >> 2) & 31);
    #pragma unroll
    for (int bkt = 0; bkt < 32; bkt++) scnt[c][bkt] = 0;
    __syncthreads();

    // pass 1: bucket counts (coalesced over c across lanes)
    for (int k = 0; k < N_TAPS; k++)
        for (int r = 0; r < R_DIM; r++) {
            float v = W_fb[(k * R_DIM + r) * R_DIM + c];
            if (v != 0.f) {
                int e = k * R_DIM + r;
                int sub = e & 1;
                int key = (((e >> 1) & 15) - cl) & 15;
                scnt[c][sub * 16 + key]++;
            }
        }

    // exclusive prefix within each parity partition; per-column max sub size
    int mymax = 0;
    #pragma unroll
    for (int sub = 0; sub < 2; sub++) {
        int acc = 0;
        #pragma unroll
        for (int bkt = 0; bkt < 16; bkt++) {
            int v = scnt[c][sub * 16 + bkt];
            scnt[c][sub * 16 + bkt] = acc;
            acc += v;
        }
        if (acc > mymax) mymax = acc;
    }
    atomicMax(&swMaxE[wg], mymax < CAP_SUB ? mymax : CAP_SUB);
    __syncthreads();

    if (c == 0) {
        int base = 0;
        for (int w = 0; w < NWARP; w++) {
            int qd = (swMaxE[w] + 3) >> 2;
            if (qd < 1) qd = 1;
            if (qd > CAP_QUAD) qd = CAP_QUAD;
            sBase[w] = base;
            g_warpBase[w]  = base;
            g_warpQuads[w] = qd;
            base += qd;
        }
    }
    __syncthreads();

    // pass 2: scatter, compensated rounding (raw word ~= true weight)
    const int base = sBase[wg];
    for (int k = 0; k < N_TAPS; k++) {
        const float twk = tw[k];
        for (int r = 0; r < R_DIM; r++) {
            float v = W_fb[(k * R_DIM + r) * R_DIM + c];
            if (v != 0.f) {
                unsigned e = (unsigned)(k * R_DIM + r);
                int sub = e & 1;
                int key = (((e >> 1) & 15) - cl) & 15;
                int j = scnt[c][sub * 16 + key]++;
                if (j < CAP_SUB) {
                    unsigned fu  = __float_as_uint(v * twk);
                    unsigned w32 = ((fu - e + 0x400u) & ~0x7FFu) | e;
                    const int lane = cl * 2 + sub;
                    g_sched[(base + (j >> 2)) * 128 + lane * 4 + (j & 3)] = w32;
                }
            }
        }
    }
}

// ---------------------------------------------------------------------------
// Main: 32 CTAs (one batch PAIR each), 512 threads, static SMEM only (20KB).
// ---------------------------------------------------------------------------
__global__ void __launch_bounds__(NTH, 1)
reservoir_kernel(const float* __restrict__ x,
                 const float* __restrict__ W_in,
                 const float* __restrict__ bias,
                 float* __restrict__ out) {
    __shared__ float2 hist[2][5 * R_DIM];   // 20480 B static, batch-packed

    const int tid  = threadIdx.x;
    const int wg   = tid >> 5;
    const int lane = tid & 31;
    const int sub  = lane & 1;                // my batch within the pair
    const int c    = wg * 16 + (lane >> 1);   // owned column
    const int bp   = blockIdx.x;              // batch pair index

    for (int i = tid; i < 2 * 5 * R_DIM; i += NTH)
        ((float2*)hist)[i] = make_float2(0.f, 0.f);

    const int QD = g_warpQuads[wg];           // uniform per warp
    const float w_in_c = W_in[c];
    const float bias_c = bias[c];

    const size_t bstride = (size_t)T_LEN * R_DIM;
    float* ob0 = out + (size_t)(2 * bp)     * bstride;   // batch 2bp
    float* ob1 = out + (size_t)(2 * bp + 1) * bstride;   // batch 2bp+1
    float* obm = sub ? ob1 : ob0;                        // my batch
    const float* xrm = x + (size_t)(2 * bp + sub) * T_LEN;

    // prefetch staging roles: threads 0-255 stage slots 1,2; 256-511 slots 3,4
    const int q    = tid >> 8;
    const int col2 = tid & 255;

    float h  = 0.f;
    float xc = __ldg(xrm);                    // x[my batch][0]
    __syncthreads();

    // my quad stream: quad p = uint4 slot [(base+p)*32 + lane]
    const uint4* sp4 = (const uint4*)g_sched + (size_t)g_warpBase[wg] * 32 + lane;

    for (int t = 0; t < T_LEN; t++) {
        const float2* cur = hist[t & 1];
        float2*       nxt = hist[(t + 1) & 1];

        // prefetch rows for step t+1, BOTH batches, via __ldcg (L2-direct)
        float p0a, p0b, p1a, p1b;
        if (q == 0) {
            p0a = (t >= 3)  ? __ldcg(ob0 + (size_t)(t - 3)  * R_DIM + col2) : 0.f;
            p0b = (t >= 3)  ? __ldcg(ob1 + (size_t)(t - 3)  * R_DIM + col2) : 0.f;
            p1a = (t >= 23) ? __ldcg(ob0 + (size_t)(t - 23) * R_DIM + col2) : 0.f;
            p1b = (t >= 23) ? __ldcg(ob1 + (size_t)(t - 23) * R_DIM + col2) : 0.f;
        } else {
            p0a = (t >= 95)  ? __ldcg(ob0 + (size_t)(t - 95)  * R_DIM + col2) : 0.f;
            p0b = (t >= 95)  ? __ldcg(ob1 + (size_t)(t - 95)  * R_DIM + col2) : 0.f;
            p1a = (t >= 167) ? __ldcg(ob0 + (size_t)(t - 167) * R_DIM + col2) : 0.f;
            p1b = (t >= 167) ? __ldcg(ob1 + (size_t)(t - 167) * R_DIM + col2) : 0.f;
        }
        const float xn = (t + 1 < T_LEN) ? __ldg(xrm + t + 1) : 0.f;

        // sparse gather: LDG.128 = 4 entries; each entry: raw word = weight,
        // LDS.64 batch-packed hist, 2 FFMA. Pads contribute denormal*h ~ 0.
        float2 a0 = make_float2(0.f, 0.f), a1 = make_float2(0.f, 0.f);
        float2 a2 = make_float2(0.f, 0.f), a3 = make_float2(0.f, 0.f);
        #pragma unroll 4
        for (int p = 0; p < QD; p++) {
            const uint4 e = __ldg(&sp4[p * 32]);
            const float2 h0 = cur[e.x & 0x7FFu];
            const float2 h1 = cur[e.y & 0x7FFu];
            const float2 h2 = cur[e.z & 0x7FFu];
            const float2 h3 = cur[e.w & 0x7FFu];
            a0.x = fmaf(__uint_as_float(e.x), h0.x, a0.x);
            a0.y = fmaf(__uint_as_float(e.x), h0.y, a0.y);
            a1.x = fmaf(__uint_as_float(e.y), h1.x, a1.x);
            a1.y = fmaf(__uint_as_float(e.y), h1.y, a1.y);
            a2.x = fmaf(__uint_as_float(e.z), h2.x, a2.x);
            a2.y = fmaf(__uint_as_float(e.z), h2.y, a2.y);
            a3.x = fmaf(__uint_as_float(e.w), h3.x, a3.x);
            a3.y = fmaf(__uint_as_float(e.w), h3.y, a3.y);
        }
        float accx = (a0.x + a1.x) + (a2.x + a3.x);   // batch 2bp
        float accy = (a0.y + a1.y) + (a2.y + a3.y);   // batch 2bp+1
        accx += __shfl_xor_sync(0xffffffffu, accx, 1);
        accy += __shfl_xor_sync(0xffffffffu, accy, 1);

        // epilogue: sub-lane owns its batch (one tanh + STG + slot0 STS each)
        const float myacc = sub ? accy : accx;
        h = 0.9f * h + 0.1f * tanhf(fmaf(xc, w_in_c, myacc) + bias_c);
        obm[(size_t)t * R_DIM + c] = h;
        // slot0 = row t: float2 word sub of column c -> smem bank = lane
        ((float*)&nxt[c])[sub] = h;

        // stage slots 1-4 (both batches, float2 STS.64, conflict-free phases)
        if (q == 0) {
            nxt[1 * R_DIM + col2] = make_float2(p0a, p0b);
            nxt[2 * R_DIM + col2] = make_float2(p1a, p1b);
        } else {
            nxt[3 * R_DIM + col2] = make_float2(p0a, p0b);
            nxt[4 * R_DIM + col2] = make_float2(p1a, p1b);
        }
        xc = xn;

        __syncthreads();   // the ONLY per-step synchronization
    }
}

// ---------------------------------------------------------------------------
extern "C" void kernel_launch(void* const* d_in, const int* in_sizes, int n_in,
                              void* d_out, int out_size) {
    const float* x           = (const float*)d_in[0];  // (64, 2048, 1)
    const float* W_in        = (const float*)d_in[1];  // (256, 1)
    const float* W_fb        = (const float*)d_in[2];  // (5, 256, 256)
    const float* tap_weights = (const float*)d_in[3];  // (5,)
    const float* bias        = (const float*)d_in[4];  // (256,)
    float* out = (float*)d_out;                        // (64, 2048, 256)

    (void)in_sizes; (void)n_in; (void)out_size;

    build_kernel<<<1, R_DIM>>>(W_fb, tap_weights);
    reservoir_kernel<<<NCTA, NTH>>>(x, W_in, bias, out);
}

// round 17
// speedup vs baseline: 1.4848x; 1.4848x over previous
#include <cuda_runtime.h>
#include <math.h>

// ---------------------------------------------------------------------------
// PhotonicDelayReservoirAdaptive — sparse delay-tap reservoir scan, sm_103a.
//
//   fb[b,s]  = sum_k softmax(tapw)[k] * sum_r h[b, t-d_k, r] * W_fb[k,r,s]
//   h_new    = 0.9*h + 0.1*tanh(x[b,t]*W_in[s] + fb[b,s] + bias[s])
//
// R16 — TWO PIPELINED CTAs PER BATCH (128 CTAs, still no per-step barrier):
//  R15 proved wall time = single-CTA step time (idle SMs!). Split each
//  batch: CTA A owns the recurrence: tap-1 entries + ~35% of d>=4 + epilogue
//  + publishes row t (flag w/ release). CTA B computes the other ~65% of
//  d>=4 partials LAGGED >=4 steps (its inputs, rows t-4.., have slack) and
//  publishes partial[t] via L2 + flag. A adds B's partial before tanh.
//  Steady state: both flag polls are single satisfied acquire-loads (3-4
//  step pipeline slack); no spinning, no barriers between CTAs.
//  * Flags zeroed by a reset kernel each launch (replay-safe).
//  * Both CTAs use the R14 gather engine: 512 thr, warp owns 16 columns,
//    2 sub-lanes/column by entry parity (bank-disjoint), rotation-sorted,
//    compensated packing (raw word = f32 weight, low 11 bits = hist index,
//    validated rel_err 8e-6), LDG.128 quads (L1-resident schedule),
//    __ldcg history (L2-direct), static SMEM hist double buffer.
// ---------------------------------------------------------------------------

#define T_LEN     2048
#define R_DIM     256
#define N_TAPS    5
#define NTH       512
#define NWARP     16
#define NBATCH    64
#define CAP_SUB   64
#define CAP_QUAD  16
#define A_PCT     35      // percent of d>=4 entries assigned to CTA A

#define SCHED_WORDS (NWARP * CAP_QUAD * 128)   // 32768 words = 128 KB each

__device__ __align__(16) unsigned g_schedA[SCHED_WORDS];
__device__ __align__(16) unsigned g_schedB[SCHED_WORDS];
__device__ int g_quadsA[NWARP];
__device__ int g_quadsB[NWARP];
__device__ int g_rowFlag[NBATCH * T_LEN];      // stamp t+1 when row t visible
__device__ int g_partialFlag[NBATCH * T_LEN];  // stamp t+1 when partial t visible
__device__ float g_partial[NBATCH * 32 * R_DIM];   // ring depth 32

__device__ __forceinline__ int ld_acquire(const int* p) {
    int v;
    asm volatile("ld.acquire.gpu.b32 %0, [%1];" : "=r"(v) : "l"(p) : "memory");
    return v;
}

// ---------------------------------------------------------------------------
// Reset: zero both flag arrays (must precede the main kernel every launch).
// ---------------------------------------------------------------------------
__global__ void reset_kernel() {
    int i = blockIdx.x * blockDim.x + threadIdx.x;
    if (i < NBATCH * T_LEN) { g_rowFlag[i] = 0; g_partialFlag[i] = 0; }
}

// ---------------------------------------------------------------------------
// Builder: 1 CTA, 256 threads, thread = column c (wg=c/16, cl=c%16).
// Emits two schedules: A = all tap-1 entries (e=r, slot0) + first 35% of
// d>=4 entries (e=k*256+r, slots1-4); B = remaining d>=4 (e'=(k-1)*256+r).
// Both parity-split + rotation-sorted + quad-interleaved [wg][quad][lane][4]
// with compensated rounding at bit 11.
// ---------------------------------------------------------------------------
__global__ void build_kernel(const float* __restrict__ W_fb,
                             const float* __restrict__ tapw) {
    __shared__ int scnt[R_DIM][32];
    __shared__ int swMax[NWARP];

    const int c  = threadIdx.x;
    const int wg = c >> 4;
    const int cl = c & 15;

    float tw[N_TAPS];
    {
        float m = tapw[0];
        #pragma unroll
        for (int k = 1; k < N_TAPS; k++) m = fmaxf(m, tapw[k]);
        float sum = 0.f;
        #pragma unroll
        for (int k = 0; k < N_TAPS; k++) { tw[k] = expf(tapw[k] - m); sum += tw[k]; }
        #pragma unroll
        for (int k = 0; k < N_TAPS; k++) tw[k] /= sum;
    }

    // count d>=4 nonzeros for the split point
    int n4 = 0;
    for (int k = 1; k < N_TAPS; k++)
        for (int r = 0; r < R_DIM; r++)
            n4 += (W_fb[(k * R_DIM + r) * R_DIM + c] != 0.f) ? 1 : 0;
    const int nA4 = (n4 * A_PCT) / 100;

    // pad-fill both schedules: word -> its lane slot (denormal value ~0,
    // hist bank = lane -> conflict-free pad reads)
    for (int i = c; i < SCHED_WORDS; i += R_DIM) {
        unsigned pad = (unsigned)((i >> 2) & 31);
        g_schedA[i] = pad;
        g_schedB[i] = pad;
    }

    // ================= schedule A =================
    if (c < NWARP) swMax[c] = 0;
    #pragma unroll
    for (int bkt = 0; bkt < 32; bkt++) scnt[c][bkt] = 0;
    __syncthreads();

    {
        int cnt4 = 0;
        for (int k = 0; k < N_TAPS; k++)
            for (int r = 0; r < R_DIM; r++) {
                float v = W_fb[(k * R_DIM + r) * R_DIM + c];
                if (v != 0.f) {
                    int take = 0, e = 0;
                    if (k == 0) { take = 1; e = r; }
                    else { if (cnt4 < nA4) { take = 1; e = k * R_DIM + r; } cnt4++; }
                    if (take) {
                        int sub = e & 1;
                        int key = (((e >> 1) & 15) - cl) & 15;
                        scnt[c][sub * 16 + key]++;
                    }
                }
            }
        int mymax = 0;
        #pragma unroll
        for (int sub = 0; sub < 2; sub++) {
            int acc = 0;
            #pragma unroll
            for (int bkt = 0; bkt < 16; bkt++) {
                int v = scnt[c][sub * 16 + bkt];
                scnt[c][sub * 16 + bkt] = acc;
                acc += v;
            }
            if (acc > mymax) mymax = acc;
        }
        atomicMax(&swMax[wg], mymax < CAP_SUB ? mymax : CAP_SUB);
        __syncthreads();
        if (c < NWARP) {
            int qd = (swMax[c] + 3) >> 2;
            g_quadsA[c] = qd < 1 ? 1 : (qd > CAP_QUAD ? CAP_QUAD : qd);
        }
        // scatter A
        cnt4 = 0;
        for (int k = 0; k < N_TAPS; k++) {
            const float twk = tw[k];
            for (int r = 0; r < R_DIM; r++) {
                float v = W_fb[(k * R_DIM + r) * R_DIM + c];
                if (v != 0.f) {
                    int take = 0; unsigned e = 0;
                    if (k == 0) { take = 1; e = (unsigned)r; }
                    else { if (cnt4 < nA4) { take = 1; e = (unsigned)(k * R_DIM + r); } cnt4++; }
                    if (take) {
                        int sub = e & 1;
                        int key = (((e >> 1) & 15) - cl) & 15;
                        int j = scnt[c][sub * 16 + key]++;
                        if (j < CAP_SUB) {
                            unsigned fu  = __float_as_uint(v * twk);
                            unsigned w32 = ((fu - e + 0x400u) & ~0x7FFu) | e;
                            int lane = cl * 2 + sub;
                            g_schedA[wg * (CAP_QUAD * 128) + (j >> 2) * 128
                                     + lane * 4 + (j & 3)] = w32;
                        }
                    }
                }
            }
        }
    }
    __syncthreads();

    // ================= schedule B =================
    if (c < NWARP) swMax[c] = 0;
    #pragma unroll
    for (int bkt = 0; bkt < 32; bkt++) scnt[c][bkt] = 0;
    __syncthreads();

    {
        int cnt4 = 0;
        for (int k = 1; k < N_TAPS; k++)
            for (int r = 0; r < R_DIM; r++) {
                float v = W_fb[(k * R_DIM + r) * R_DIM + c];
                if (v != 0.f) {
                    if (cnt4 >= nA4) {
                        int e = (k - 1) * R_DIM + r;
                        int sub = e & 1;
                        int key = (((e >> 1) & 15) - cl) & 15;
                        scnt[c][sub * 16 + key]++;
                    }
                    cnt4++;
                }
            }
        int mymax = 0;
        #pragma unroll
        for (int sub = 0; sub < 2; sub++) {
            int acc = 0;
            #pragma unroll
            for (int bkt = 0; bkt < 16; bkt++) {
                int v = scnt[c][sub * 16 + bkt];
                scnt[c][sub * 16 + bkt] = acc;
                acc += v;
            }
            if (acc > mymax) mymax = acc;
        }
        atomicMax(&swMax[wg], mymax < CAP_SUB ? mymax : CAP_SUB);
        __syncthreads();
        if (c < NWARP) {
            int qd = (swMax[c] + 3) >> 2;
            g_quadsB[c] = qd < 1 ? 1 : (qd > CAP_QUAD ? CAP_QUAD : qd);
        }
        // scatter B
        cnt4 = 0;
        for (int k = 1; k < N_TAPS; k++) {
            const float twk = tw[k];
            for (int r = 0; r < R_DIM; r++) {
                float v = W_fb[(k * R_DIM + r) * R_DIM + c];
                if (v != 0.f) {
                    if (cnt4 >= nA4) {
                        unsigned e = (unsigned)((k - 1) * R_DIM + r);
                        int sub = e & 1;
                        int key = (((e >> 1) & 15) - cl) & 15;
                        int j = scnt[c][sub * 16 + key]++;
                        if (j < CAP_SUB) {
                            unsigned fu  = __float_as_uint(v * twk);
                            unsigned w32 = ((fu - e + 0x400u) & ~0x7FFu) | e;
                            int lane = cl * 2 + sub;
                            g_schedB[wg * (CAP_QUAD * 128) + (j >> 2) * 128
                                     + lane * 4 + (j & 3)] = w32;
                        }
                    }
                    cnt4++;
                }
            }
        }
    }
}

// ---------------------------------------------------------------------------
// Main: 128 CTAs = 64 A (recurrence owners) + 64 B (lagged helpers).
// ---------------------------------------------------------------------------
__global__ void __launch_bounds__(NTH, 1)
reservoir_kernel(const float* __restrict__ x,
                 const float* __restrict__ W_in,
                 const float* __restrict__ bias,
                 float* __restrict__ out) {
    __shared__ float hist[2][5 * R_DIM];   // A uses 5 slots; B first 4

    const int tid  = threadIdx.x;
    const int wg   = tid >> 5;
    const int lane = tid & 31;
    const int c    = wg * 16 + (lane >> 1);
    const bool isA = (blockIdx.x < NBATCH);
    const int b    = isA ? blockIdx.x : (int)blockIdx.x - NBATCH;

    for (int i = tid; i < 2 * 5 * R_DIM; i += NTH) ((float*)hist)[i] = 0.f;

    const size_t bstride = (size_t)T_LEN * R_DIM;
    float* ob = out + (size_t)b * bstride;
    int*   rowFlag = g_rowFlag + b * T_LEN;
    int*   parFlag = g_partialFlag + b * T_LEN;
    float* parBuf  = g_partial + b * 32 * R_DIM;
    const int q    = tid >> 8;        // 0 / 1: prefetch staging halves
    const int col2 = tid & 255;

    __syncthreads();

    if (isA) {
        // ============ role A: recurrence owner ============
        const int QD = g_quadsA[wg];
        const float w_in_c = W_in[c];
        const float bias_c = bias[c];
        const uint4* sp4 = (const uint4*)g_schedA + (size_t)wg * (CAP_QUAD * 32) + lane;

        float h  = 0.f;
        float xc = __ldg(x + (size_t)b * T_LEN);

        for (int t = 0; t < T_LEN; t++) {
            const float* cur = hist[t & 1];
            float*       nxt = hist[(t + 1) & 1];

            // prefetch own history rows for step t+1 (L2-direct)
            float n0, n1;
            if (q == 0) {
                n0 = (t >= 3)  ? __ldcg(ob + (size_t)(t - 3)  * R_DIM + col2) : 0.f;
                n1 = (t >= 23) ? __ldcg(ob + (size_t)(t - 23) * R_DIM + col2) : 0.f;
            } else {
                n0 = (t >= 95)  ? __ldcg(ob + (size_t)(t - 95)  * R_DIM + col2) : 0.f;
                n1 = (t >= 167) ? __ldcg(ob + (size_t)(t - 167) * R_DIM + col2) : 0.f;
            }
            const float xn = (t + 1 < T_LEN) ? __ldg(x + (size_t)b * T_LEN + t + 1) : 0.f;

            // own gather (tap-1 + A-share of d>=4)
            float a0 = 0.f, a1 = 0.f, a2 = 0.f, a3 = 0.f;
            #pragma unroll 4
            for (int p = 0; p < QD; p++) {
                const uint4 e = __ldg(&sp4[p * 32]);
                a0 = fmaf(__uint_as_float(e.x), cur[e.x & 0x7FFu], a0);
                a1 = fmaf(__uint_as_float(e.y), cur[e.y & 0x7FFu], a1);
                a2 = fmaf(__uint_as_float(e.z), cur[e.z & 0x7FFu], a2);
                a3 = fmaf(__uint_as_float(e.w), cur[e.w & 0x7FFu], a3);
            }
            float acc = (a0 + a1) + (a2 + a3);
            acc += __shfl_xor_sync(0xffffffffu, acc, 1);

            // add B's partial for step t (acquire; steady-state no spin)
            while (ld_acquire(&parFlag[t]) < t + 1) { }
            acc += __ldcg(&parBuf[((t & 31) << 8) + c]);

            // epilogue: both sub-lanes compute h; sub0 stores
            h = 0.9f * h + 0.1f * tanhf(fmaf(xc, w_in_c, acc) + bias_c);
            if ((lane & 1) == 0) {
                ob[(size_t)t * R_DIM + c] = h;
                nxt[c] = h;                       // slot0 = row t (d=1)
            }
            if (q == 0) { nxt[1 * R_DIM + col2] = n0; nxt[2 * R_DIM + col2] = n1; }
            else        { nxt[3 * R_DIM + col2] = n0; nxt[4 * R_DIM + col2] = n1; }
            xc = xn;

            __syncthreads();
            // publish row t (release)
            if (tid == 0) { __threadfence(); atomicExch(&rowFlag[t], t + 1); }
        }
    } else {
        // ============ role B: lagged d>=4 helper ============
        const int QD = g_quadsB[wg];
        const uint4* sp4 = (const uint4*)g_schedB + (size_t)wg * (CAP_QUAD * 32) + lane;

        for (int v = 0; v < T_LEN; v++) {
            const float* cur = hist[v & 1];
            float*       nxt = hist[(v + 1) & 1];

            // wait for A's row v-3 (newest needed to stage for step v+1),
            // then prefetch rows for v+1 (older rows implied by monotone flags)
            const int rk = v - 3;
            if (rk >= 0) { while (ld_acquire(&rowFlag[rk]) < rk + 1) { } }
            float n0, n1;
            if (q == 0) {
                n0 = (v >= 3)  ? __ldcg(ob + (size_t)(v - 3)  * R_DIM + col2) : 0.f;
                n1 = (v >= 23) ? __ldcg(ob + (size_t)(v - 23) * R_DIM + col2) : 0.f;
            } else {
                n0 = (v >= 95)  ? __ldcg(ob + (size_t)(v - 95)  * R_DIM + col2) : 0.f;
                n1 = (v >= 167) ? __ldcg(ob + (size_t)(v - 167) * R_DIM + col2) : 0.f;
            }

            // gather B-share of d>=4 against cur (slots 0-3 = delays 4,24,96,168)
            float a0 = 0.f, a1 = 0.f, a2 = 0.f, a3 = 0.f;
            #pragma unroll 4
            for (int p = 0; p < QD; p++) {
                const uint4 e = __ldg(&sp4[p * 32]);
                a0 = fmaf(__uint_as_float(e.x), cur[e.x & 0x7FFu], a0);
                a1 = fmaf(__uint_as_float(e.y), cur[e.y & 0x7FFu], a1);
                a2 = fmaf(__uint_as_float(e.z), cur[e.z & 0x7FFu], a2);
                a3 = fmaf(__uint_as_float(e.w), cur[e.w & 0x7FFu], a3);
            }
            float acc = (a0 + a1) + (a2 + a3);
            acc += __shfl_xor_sync(0xffffffffu, acc, 1);

            if ((lane & 1) == 0)
                __stcg(&parBuf[((v & 31) << 8) + c], acc);

            // stage rows for step v+1: slots 0-3 = delays {4,24,96,168}
            if (q == 0) { nxt[0 * R_DIM + col2] = n0; nxt[1 * R_DIM + col2] = n1; }
            else        { nxt[2 * R_DIM + col2] = n0; nxt[3 * R_DIM + col2] = n1; }

            __syncthreads();
            // publish partial v (release)
            if (tid == 0) { __threadfence(); atomicExch(&parFlag[v], v + 1); }
        }
    }
}

// ---------------------------------------------------------------------------
extern "C" void kernel_launch(void* const* d_in, const int* in_sizes, int n_in,
                              void* d_out, int out_size) {
    const float* x           = (const float*)d_in[0];  // (64, 2048, 1)
    const float* W_in        = (const float*)d_in[1];  // (256, 1)
    const float* W_fb        = (const float*)d_in[2];  // (5, 256, 256)
    const float* tap_weights = (const float*)d_in[3];  // (5,)
    const float* bias        = (const float*)d_in[4];  // (256,)
    float* out = (float*)d_out;                        // (64, 2048, 256)

    (void)in_sizes; (void)n_in; (void)out_size;

    reset_kernel<<<(NBATCH * T_LEN + 255) / 256, 256>>>();
    build_kernel<<<1, R_DIM>>>(W_fb, tap_weights);
    reservoir_kernel<<<2 * NBATCH, NTH>>>(x, W_in, bias, out);
}